// round 14
// baseline (speedup 1.0000x reference)
#include <cuda_runtime.h>
#include <cuda_fp16.h>
#include <cstdint>

#define N_NODES 50000
#define E_EDGES 800000
#define NHEAD 4
#define C 64
#define DIN 32
#define DOUT 128
#define HC 256   // NHEAD * C

#define CHUNK 16
#define NCHUNK ((N_NODES + CHUNK - 1) / CHUNK)   // 3125

// ---------------- device scratch ----------------------------------------------------------
__device__ int    g_is64;
__device__ int    g_cnt[N_NODES];
__device__ int    g_chunksum[NCHUNK];
__device__ int    g_chunkpre[NCHUNK];
__device__ int    g_rowptr[N_NODES + 1];
__device__ int    g_cursor[N_NODES];
__device__ int    g_csrc[E_EDGES];
__device__ __half g_xl[N_NODES * HC];     // fp16 storage, fp32 math
__device__ __half g_xr[N_NODES * HC];
__device__ float  g_h[N_NODES * C];
__device__ float  g_agg[N_NODES * C];

// ---------------- helpers ------------------------------------------------------------------
__device__ __forceinline__ unsigned long long pack2(float lo, float hi) {
    unsigned long long r;
    asm("mov.b64 %0, {%1,%2};" : "=l"(r) : "f"(lo), "f"(hi));
    return r;
}
__device__ __forceinline__ unsigned long long fma2(unsigned long long a,
                                                   unsigned long long b,
                                                   unsigned long long c) {
    unsigned long long d;
    asm("fma.rn.f32x2 %0, %1, %2, %3;" : "=l"(d) : "l"(a), "l"(b), "l"(c));
    return d;
}
__device__ __forceinline__ float hsum2(unsigned long long v) {
    float lo, hi;
    asm("mov.b64 {%0,%1}, %2;" : "=f"(lo), "=f"(hi) : "l"(v));
    return lo + hi;
}
// 8 consecutive halves (16B aligned) -> two float4, by value (registerizable)
struct F8 { float4 lo, hi; };
__device__ __forceinline__ F8 ldh8(const __half* p) {
    uint4 raw = *(const uint4*)p;
    const __half2* h = (const __half2*)&raw;
    float2 f0 = __half22float2(h[0]);
    float2 f1 = __half22float2(h[1]);
    float2 f2 = __half22float2(h[2]);
    float2 f3 = __half22float2(h[3]);
    F8 r;
    r.lo = make_float4(f0.x, f0.y, f1.x, f1.y);
    r.hi = make_float4(f2.x, f2.y, f3.x, f3.y);
    return r;
}

// ---------------- K0: zero histogram + detect dtype (fused) --------------------------------
__global__ void k_zero_cnt(const int* __restrict__ ei32) {
    int i = blockIdx.x * blockDim.x + threadIdx.x;
    if (i < N_NODES) g_cnt[i] = 0;
    if (i == 0) {
        int odd_zero = 1;
        for (int j = 1; j < 64; j += 2)
            if (ei32[j] != 0) { odd_zero = 0; break; }
        g_is64 = odd_zero;   // int64 viewed as int32: odd positions all zero
    }
}

// ---------------- K1: degree histogram, 2 edges/thread, vector index loads -----------------
__global__ void k_hist(const void* __restrict__ ei) {
    int p2 = blockIdx.x * blockDim.x + threadIdx.x;   // pair index
    int e = p2 * 2;
    if (e >= E_EDGES) return;
    if (g_is64) {
        longlong2 d = ((const longlong2*)((const long long*)ei + E_EDGES))[p2];
        atomicAdd(&g_cnt[(int)d.x], 1);
        if (e + 1 < E_EDGES) atomicAdd(&g_cnt[(int)d.y], 1);
    } else {
        int2 d = ((const int2*)((const int*)ei + E_EDGES))[p2];
        atomicAdd(&g_cnt[d.x], 1);
        if (e + 1 < E_EDGES) atomicAdd(&g_cnt[d.y], 1);
    }
}

// ---------------- K2a: per-chunk sums ------------------------------------------------------
__global__ void k_chunk_sum() {
    int c = blockIdx.x * blockDim.x + threadIdx.x;
    if (c >= NCHUNK) return;
    int b = c * CHUNK;
    int e = min(b + CHUNK, N_NODES);
    int s = 0;
    #pragma unroll 4
    for (int i = b; i < e; i++) s += g_cnt[i];
    g_chunksum[c] = s;
}

// ---------------- K2b: scan chunk sums in one block ----------------------------------------
#define SCAN_T 1024
#define PER_T  ((NCHUNK + SCAN_T - 1) / SCAN_T)   // 4
__global__ void __launch_bounds__(SCAN_T) k_scan_chunks() {
    __shared__ int part[SCAN_T];
    int t = threadIdx.x;
    int v[PER_T];
    int s = 0;
    #pragma unroll
    for (int j = 0; j < PER_T; j++) {
        int c = t * PER_T + j;
        v[j] = (c < NCHUNK) ? g_chunksum[c] : 0;
        s += v[j];
    }
    part[t] = s;
    __syncthreads();
    for (int off = 1; off < SCAN_T; off <<= 1) {
        int u = (t >= off) ? part[t - off] : 0;
        __syncthreads();
        part[t] += u;
        __syncthreads();
    }
    int pre = (t == 0) ? 0 : part[t - 1];
    #pragma unroll
    for (int j = 0; j < PER_T; j++) {
        int c = t * PER_T + j;
        if (c < NCHUNK) g_chunkpre[c] = pre;
        pre += v[j];
    }
    if (t == SCAN_T - 1) g_rowptr[N_NODES] = part[SCAN_T - 1];
}

// ---------------- K2c: expand rowptr/cursor ------------------------------------------------
__global__ void k_fill_rowptr() {
    int c = blockIdx.x * blockDim.x + threadIdx.x;
    if (c >= NCHUNK) return;
    int b = c * CHUNK;
    int e = min(b + CHUNK, N_NODES);
    int pre = g_chunkpre[c];
    for (int i = b; i < e; i++) {
        g_rowptr[i] = pre;
        g_cursor[i] = pre;
        pre += g_cnt[i];
    }
}

// ---------------- K3: CSR fill, 2 edges/thread, vector index loads -------------------------
__global__ void k_fill(const void* __restrict__ ei) {
    int p2 = blockIdx.x * blockDim.x + threadIdx.x;
    int e = p2 * 2;
    if (e >= E_EDGES) return;
    int s0, d0, s1 = -1, d1 = -1;
    if (g_is64) {
        const long long* p = (const long long*)ei;
        longlong2 sp = ((const longlong2*)p)[p2];
        longlong2 dp = ((const longlong2*)(p + E_EDGES))[p2];
        s0 = (int)sp.x; d0 = (int)dp.x;
        if (e + 1 < E_EDGES) { s1 = (int)sp.y; d1 = (int)dp.y; }
    } else {
        const int* p = (const int*)ei;
        int2 sp = ((const int2*)p)[p2];
        int2 dp = ((const int2*)(p + E_EDGES))[p2];
        s0 = sp.x; d0 = dp.x;
        if (e + 1 < E_EDGES) { s1 = sp.y; d1 = dp.y; }
    }
    int pos0 = atomicAdd(&g_cursor[d0], 1);
    g_csrc[pos0] = s0;
    if (d1 >= 0) {
        int pos1 = atomicAdd(&g_cursor[d1], 1);
        g_csrc[pos1] = s1;
    }
}

// ---------------- K4: node linear, both matrices in ONE launch (blockIdx.y = which) --------
#define NL_TILE 16
__global__ void __launch_bounds__(256) k_node_linear(const float* __restrict__ x,
                                                     const float* __restrict__ Wl,
                                                     const float* __restrict__ Wr) {
    int which = blockIdx.y;
    const float* W = which ? Wr : Wl;
    __half* outh = which ? g_xr : g_xl;   // device-side selection (no host symbol)
    __shared__ float sw[256 * 33];
    __shared__ float sx[NL_TILE * DIN];
    int o = threadIdx.x;
    unsigned long long w[DIN / 2];
    for (int i = threadIdx.x; i < 256 * DIN; i += 256)
        sw[(i >> 5) * 33 + (i & 31)] = W[i];
    __syncthreads();
    #pragma unroll
    for (int k = 0; k < DIN / 2; k++) w[k] = pack2(sw[o * 33 + 2 * k], sw[o * 33 + 2 * k + 1]);

    for (int base = blockIdx.x * NL_TILE; base < N_NODES; base += gridDim.x * NL_TILE) {
        int nn = min(NL_TILE, N_NODES - base);
        __syncthreads();
        for (int i = threadIdx.x; i < nn * DIN; i += 256)
            sx[i] = x[base * DIN + i];
        __syncthreads();
        for (int j = 0; j < nn; j++) {
            const unsigned long long* sxp = (const unsigned long long*)(sx + j * DIN);
            unsigned long long aA = 0, aB = 0;
            #pragma unroll
            for (int k = 0; k < DIN / 2; k += 2) {
                aA = fma2(w[k],     sxp[k],     aA);
                aB = fma2(w[k + 1], sxp[k + 1], aB);
            }
            outh[(size_t)(base + j) * HC + o] = __float2half(hsum2(aA) + hsum2(aB));
        }
    }
}

// ---------------- K5: node-centric fused GAT (head-per-8-lane, 4-edge unroll) --------------
__global__ void __launch_bounds__(256) k_gat_node(const float* __restrict__ att) {
    __shared__ float satt[HC];
    if (threadIdx.x < HC) satt[threadIdx.x] = att[threadIdx.x];
    __syncthreads();
    int n = blockIdx.x * 8 + (threadIdx.x >> 5);
    if (n >= N_NODES) return;
    int l = threadIdx.x & 31;
    int h = l >> 3, g = l & 7;
    int off = h * C + 8 * g;
    int beg = g_rowptr[n], end = g_rowptr[n + 1];

    F8 b = ldh8(g_xr + (size_t)n * HC + off);
    float4 tlo = *(const float4*)(satt + off);
    float4 thi = *(const float4*)(satt + off + 4);

    float4 acc_lo = {0.f,0.f,0.f,0.f}, acc_hi = {0.f,0.f,0.f,0.f};
    float den = 0.f;

    #define GAT_LOGIT8(A, P) do {                                              \
        float v_;                                                              \
        v_ = A.lo.x + b.lo.x; v_ = v_ > 0.f ? v_ : 0.2f * v_; P += v_ * tlo.x; \
        v_ = A.lo.y + b.lo.y; v_ = v_ > 0.f ? v_ : 0.2f * v_; P += v_ * tlo.y; \
        v_ = A.lo.z + b.lo.z; v_ = v_ > 0.f ? v_ : 0.2f * v_; P += v_ * tlo.z; \
        v_ = A.lo.w + b.lo.w; v_ = v_ > 0.f ? v_ : 0.2f * v_; P += v_ * tlo.w; \
        v_ = A.hi.x + b.hi.x; v_ = v_ > 0.f ? v_ : 0.2f * v_; P += v_ * thi.x; \
        v_ = A.hi.y + b.hi.y; v_ = v_ > 0.f ? v_ : 0.2f * v_; P += v_ * thi.y; \
        v_ = A.hi.z + b.hi.z; v_ = v_ > 0.f ? v_ : 0.2f * v_; P += v_ * thi.z; \
        v_ = A.hi.w + b.hi.w; v_ = v_ > 0.f ? v_ : 0.2f * v_; P += v_ * thi.w; \
    } while (0)

    #define GAT_ACCUM8(A, EX) do {                                           \
        acc_lo.x += A.lo.x * EX; acc_lo.y += A.lo.y * EX;                    \
        acc_lo.z += A.lo.z * EX; acc_lo.w += A.lo.w * EX;                    \
        acc_hi.x += A.hi.x * EX; acc_hi.y += A.hi.y * EX;                    \
        acc_hi.z += A.hi.z * EX; acc_hi.w += A.hi.w * EX;                    \
    } while (0)

    int i = beg;
    for (; i + 3 < end; i += 4) {                     // MLP = 4 gathers in flight
        int s0 = __ldg(&g_csrc[i]);
        int s1 = __ldg(&g_csrc[i + 1]);
        int s2 = __ldg(&g_csrc[i + 2]);
        int s3 = __ldg(&g_csrc[i + 3]);
        F8 a0 = ldh8(g_xl + (size_t)s0 * HC + off);
        F8 a1 = ldh8(g_xl + (size_t)s1 * HC + off);
        F8 a2 = ldh8(g_xl + (size_t)s2 * HC + off);
        F8 a3 = ldh8(g_xl + (size_t)s3 * HC + off);
        float p0 = 0.f, p1 = 0.f, p2 = 0.f, p3 = 0.f;
        GAT_LOGIT8(a0, p0);
        GAT_LOGIT8(a1, p1);
        GAT_LOGIT8(a2, p2);
        GAT_LOGIT8(a3, p3);
        #pragma unroll
        for (int s = 4; s >= 1; s >>= 1) {
            p0 += __shfl_xor_sync(0xffffffffu, p0, s);
            p1 += __shfl_xor_sync(0xffffffffu, p1, s);
            p2 += __shfl_xor_sync(0xffffffffu, p2, s);
            p3 += __shfl_xor_sync(0xffffffffu, p3, s);
        }
        float e0 = __expf(p0), e1 = __expf(p1), e2 = __expf(p2), e3 = __expf(p3);
        GAT_ACCUM8(a0, e0);
        GAT_ACCUM8(a1, e1);
        GAT_ACCUM8(a2, e2);
        GAT_ACCUM8(a3, e3);
        den += (e0 + e1) + (e2 + e3);
    }
    for (; i < end; i++) {
        int src = __ldg(&g_csrc[i]);
        F8 a = ldh8(g_xl + (size_t)src * HC + off);
        float p = 0.f;
        GAT_LOGIT8(a, p);
        #pragma unroll
        for (int s = 4; s >= 1; s >>= 1)
            p += __shfl_xor_sync(0xffffffffu, p, s);
        float ex = __expf(p);
        GAT_ACCUM8(a, ex);
        den += ex;
    }
    #undef GAT_LOGIT8
    #undef GAT_ACCUM8

    // normalize by this head's denom, then sum heads across lanes g, 8+g, 16+g, 24+g
    float inv = 1.0f / (den + 1e-16f);
    #define HEADSUM(F) do {                                                  \
        F *= inv;                                                            \
        F += __shfl_xor_sync(0xffffffffu, F, 8);                             \
        F += __shfl_xor_sync(0xffffffffu, F, 16);                            \
    } while (0)
    HEADSUM(acc_lo.x); HEADSUM(acc_lo.y); HEADSUM(acc_lo.z); HEADSUM(acc_lo.w);
    HEADSUM(acc_hi.x); HEADSUM(acc_hi.y); HEADSUM(acc_hi.z); HEADSUM(acc_hi.w);
    #undef HEADSUM

    if (l < 8) {                                 // lanes 0..7 write channels 8l..8l+8
        float deg = (float)(end - beg);
        float dinv = deg > 0.f ? rsqrtf(deg) : 0.f;
        float4 o0, o1;
        float m;
        m = 0.25f * acc_lo.x; m = m > 0.f ? m : expm1f(m); o0.x = m * dinv;
        m = 0.25f * acc_lo.y; m = m > 0.f ? m : expm1f(m); o0.y = m * dinv;
        m = 0.25f * acc_lo.z; m = m > 0.f ? m : expm1f(m); o0.z = m * dinv;
        m = 0.25f * acc_lo.w; m = m > 0.f ? m : expm1f(m); o0.w = m * dinv;
        m = 0.25f * acc_hi.x; m = m > 0.f ? m : expm1f(m); o1.x = m * dinv;
        m = 0.25f * acc_hi.y; m = m > 0.f ? m : expm1f(m); o1.y = m * dinv;
        m = 0.25f * acc_hi.z; m = m > 0.f ? m : expm1f(m); o1.z = m * dinv;
        m = 0.25f * acc_hi.w; m = m > 0.f ? m : expm1f(m); o1.w = m * dinv;
        float4* dst = (float4*)(g_h + (size_t)n * C + 8 * l);
        dst[0] = o0;
        dst[1] = o1;
    }
}

// ---------------- K6: node-centric GCN aggregate (4-edge unroll) ---------------------------
__global__ void __launch_bounds__(256) k_gcn_node() {
    int n = blockIdx.x * 8 + (threadIdx.x >> 5);
    if (n >= N_NODES) return;
    int l = threadIdx.x & 31;
    int beg = g_rowptr[n], end = g_rowptr[n + 1];
    float ax = 0.f, ay = 0.f;
    int i = beg;
    for (; i + 3 < end; i += 4) {
        int s0 = __ldg(&g_csrc[i]);
        int s1 = __ldg(&g_csrc[i + 1]);
        int s2 = __ldg(&g_csrc[i + 2]);
        int s3 = __ldg(&g_csrc[i + 3]);
        float2 v0 = ((const float2*)(g_h + (size_t)s0 * C))[l];
        float2 v1 = ((const float2*)(g_h + (size_t)s1 * C))[l];
        float2 v2 = ((const float2*)(g_h + (size_t)s2 * C))[l];
        float2 v3 = ((const float2*)(g_h + (size_t)s3 * C))[l];
        ax += (v0.x + v1.x) + (v2.x + v3.x);
        ay += (v0.y + v1.y) + (v2.y + v3.y);
    }
    for (; i < end; i++) {
        int src = __ldg(&g_csrc[i]);
        float2 v = ((const float2*)(g_h + (size_t)src * C))[l];
        ax += v.x; ay += v.y;
    }
    float deg = (float)(end - beg);
    float dinv = deg > 0.f ? rsqrtf(deg) : 0.f;
    float2 o; o.x = ax * dinv; o.y = ay * dinv;
    ((float2*)(g_agg + (size_t)n * C))[l] = o;
}

// ---------------- K7: final linear (f32x2) -------------------------------------------------
#define OL_TILE 8
__global__ void __launch_bounds__(128) k_out_linear(const float* __restrict__ Wg,
                                                    float* __restrict__ out) {
    __shared__ float sw[DOUT * 65];
    __shared__ float sh[OL_TILE * C];
    int o = threadIdx.x;
    unsigned long long wg[C / 2];
    for (int i = threadIdx.x; i < DOUT * C; i += 128)
        sw[(i >> 6) * 65 + (i & 63)] = Wg[i];
    __syncthreads();
    #pragma unroll
    for (int k = 0; k < C / 2; k++) wg[k] = pack2(sw[o * 65 + 2 * k], sw[o * 65 + 2 * k + 1]);

    for (int base = blockIdx.x * OL_TILE; base < N_NODES; base += gridDim.x * OL_TILE) {
        int nn = min(OL_TILE, N_NODES - base);
        __syncthreads();
        for (int i = threadIdx.x; i < nn * C; i += 128)
            sh[i] = g_agg[(size_t)base * C + i];
        __syncthreads();
        for (int j = 0; j < nn; j++) {
            const unsigned long long* shp = (const unsigned long long*)(sh + j * C);
            unsigned long long sA = 0, sB = 0;
            #pragma unroll
            for (int k = 0; k < C / 2; k += 2) {
                sA = fma2(wg[k],     shp[k],     sA);
                sB = fma2(wg[k + 1], shp[k + 1], sB);
            }
            out[(size_t)(base + j) * DOUT + o] = hsum2(sA) + hsum2(sB);
        }
    }
}

// ---------------- launch -------------------------------------------------------------------
extern "C" void kernel_launch(void* const* d_in, const int* in_sizes, int n_in,
                              void* d_out, int out_size) {
    const float* x   = (const float*)d_in[0];
    const void*  ei  = d_in[1];
    const float* Wl  = (const float*)d_in[2];
    const float* Wr  = (const float*)d_in[3];
    const float* att = (const float*)d_in[4];
    const float* Wg  = (const float*)d_in[5];
    float* out = (float*)d_out;
    (void)in_sizes; (void)n_in; (void)out_size;

    const int NPAIR = (E_EDGES / 2 + 255) / 256;   // 2 edges per thread

    k_zero_cnt<<<(N_NODES + 255) / 256, 256>>>((const int*)ei);
    k_hist<<<NPAIR, 256>>>(ei);
    k_chunk_sum<<<(NCHUNK + 255) / 256, 256>>>();
    k_scan_chunks<<<1, SCAN_T>>>();
    k_fill_rowptr<<<(NCHUNK + 255) / 256, 256>>>();
    k_fill<<<NPAIR, 256>>>(ei);
    k_node_linear<<<dim3(1184, 2), 256>>>(x, Wl, Wr);
    k_gat_node<<<(N_NODES + 7) / 8, 256>>>(att);
    k_gcn_node<<<(N_NODES + 7) / 8, 256>>>();
    k_out_linear<<<1184, 128>>>(Wg, out);
}

// round 15
// speedup vs baseline: 1.0393x; 1.0393x over previous
#include <cuda_runtime.h>
#include <cuda_fp16.h>
#include <cstdint>

#define N_NODES 50000
#define E_EDGES 800000
#define NHEAD 4
#define C 64
#define DIN 32
#define DOUT 128
#define HC 256   // NHEAD * C

#define CHUNK 16
#define NCHUNK ((N_NODES + CHUNK - 1) / CHUNK)   // 3125

// ---------------- device scratch ----------------------------------------------------------
__device__ int    g_is64;
__device__ int    g_cnt[N_NODES];
__device__ int    g_chunksum[NCHUNK];
__device__ int    g_chunkpre[NCHUNK];
__device__ int    g_rowptr[N_NODES + 1];
__device__ int    g_cursor[N_NODES];
__device__ int    g_csrc[E_EDGES];
__device__ __half g_xl[N_NODES * HC];     // fp16 storage, fp32 math
__device__ __half g_xr[N_NODES * HC];
__device__ float  g_h[N_NODES * C];
__device__ float  g_agg[N_NODES * C];

// ---------------- helpers ------------------------------------------------------------------
__device__ __forceinline__ unsigned long long pack2(float lo, float hi) {
    unsigned long long r;
    asm("mov.b64 %0, {%1,%2};" : "=l"(r) : "f"(lo), "f"(hi));
    return r;
}
__device__ __forceinline__ unsigned long long fma2(unsigned long long a,
                                                   unsigned long long b,
                                                   unsigned long long c) {
    unsigned long long d;
    asm("fma.rn.f32x2 %0, %1, %2, %3;" : "=l"(d) : "l"(a), "l"(b), "l"(c));
    return d;
}
__device__ __forceinline__ float hsum2(unsigned long long v) {
    float lo, hi;
    asm("mov.b64 {%0,%1}, %2;" : "=f"(lo), "=f"(hi) : "l"(v));
    return lo + hi;
}
// 8 consecutive halves (16B aligned) -> two float4, by value (registerizable)
struct F8 { float4 lo, hi; };
__device__ __forceinline__ F8 ldh8(const __half* p) {
    uint4 raw = *(const uint4*)p;
    const __half2* h = (const __half2*)&raw;
    float2 f0 = __half22float2(h[0]);
    float2 f1 = __half22float2(h[1]);
    float2 f2 = __half22float2(h[2]);
    float2 f3 = __half22float2(h[3]);
    F8 r;
    r.lo = make_float4(f0.x, f0.y, f1.x, f1.y);
    r.hi = make_float4(f2.x, f2.y, f3.x, f3.y);
    return r;
}

// ---------------- K0: zero histogram + detect dtype (fused) --------------------------------
__global__ void k_zero_cnt(const int* __restrict__ ei32) {
    int i = blockIdx.x * blockDim.x + threadIdx.x;
    if (i < N_NODES) g_cnt[i] = 0;
    if (i == 0) {
        int odd_zero = 1;
        for (int j = 1; j < 64; j += 2)
            if (ei32[j] != 0) { odd_zero = 0; break; }
        g_is64 = odd_zero;   // int64 viewed as int32: odd positions all zero
    }
}

// ---------------- K1: degree histogram straight from ei (1 edge/thread) --------------------
__global__ void k_hist(const void* __restrict__ ei) {
    int e = blockIdx.x * blockDim.x + threadIdx.x;
    if (e >= E_EDGES) return;
    int d = g_is64 ? (int)((const long long*)ei)[E_EDGES + e]
                   : ((const int*)ei)[E_EDGES + e];
    atomicAdd(&g_cnt[d], 1);
}

// ---------------- K2a: per-chunk sums ------------------------------------------------------
__global__ void k_chunk_sum() {
    int c = blockIdx.x * blockDim.x + threadIdx.x;
    if (c >= NCHUNK) return;
    int b = c * CHUNK;
    int e = min(b + CHUNK, N_NODES);
    int s = 0;
    #pragma unroll 4
    for (int i = b; i < e; i++) s += g_cnt[i];
    g_chunksum[c] = s;
}

// ---------------- K2b: scan chunk sums in one block ----------------------------------------
#define SCAN_T 1024
#define PER_T  ((NCHUNK + SCAN_T - 1) / SCAN_T)   // 4
__global__ void __launch_bounds__(SCAN_T) k_scan_chunks() {
    __shared__ int part[SCAN_T];
    int t = threadIdx.x;
    int v[PER_T];
    int s = 0;
    #pragma unroll
    for (int j = 0; j < PER_T; j++) {
        int c = t * PER_T + j;
        v[j] = (c < NCHUNK) ? g_chunksum[c] : 0;
        s += v[j];
    }
    part[t] = s;
    __syncthreads();
    for (int off = 1; off < SCAN_T; off <<= 1) {
        int u = (t >= off) ? part[t - off] : 0;
        __syncthreads();
        part[t] += u;
        __syncthreads();
    }
    int pre = (t == 0) ? 0 : part[t - 1];
    #pragma unroll
    for (int j = 0; j < PER_T; j++) {
        int c = t * PER_T + j;
        if (c < NCHUNK) g_chunkpre[c] = pre;
        pre += v[j];
    }
    if (t == SCAN_T - 1) g_rowptr[N_NODES] = part[SCAN_T - 1];
}

// ---------------- K2c: expand rowptr/cursor ------------------------------------------------
__global__ void k_fill_rowptr() {
    int c = blockIdx.x * blockDim.x + threadIdx.x;
    if (c >= NCHUNK) return;
    int b = c * CHUNK;
    int e = min(b + CHUNK, N_NODES);
    int pre = g_chunkpre[c];
    for (int i = b; i < e; i++) {
        g_rowptr[i] = pre;
        g_cursor[i] = pre;
        pre += g_cnt[i];
    }
}

// ---------------- K3: CSR fill straight from ei (1 edge/thread) ----------------------------
__global__ void k_fill(const void* __restrict__ ei) {
    int e = blockIdx.x * blockDim.x + threadIdx.x;
    if (e >= E_EDGES) return;
    int s, d;
    if (g_is64) {
        const long long* p = (const long long*)ei;
        s = (int)p[e];
        d = (int)p[E_EDGES + e];
    } else {
        const int* p = (const int*)ei;
        s = p[e];
        d = p[E_EDGES + e];
    }
    int pos = atomicAdd(&g_cursor[d], 1);
    g_csrc[pos] = s;
}

// ---------------- K4: node linear, both matrices in ONE launch (blockIdx.y = which) --------
#define NL_TILE 16
__global__ void __launch_bounds__(256) k_node_linear(const float* __restrict__ x,
                                                     const float* __restrict__ Wl,
                                                     const float* __restrict__ Wr) {
    int which = blockIdx.y;
    const float* W = which ? Wr : Wl;
    __half* outh = which ? g_xr : g_xl;   // device-side selection (no host symbol)
    __shared__ float sw[256 * 33];
    __shared__ float sx[NL_TILE * DIN];
    int o = threadIdx.x;
    unsigned long long w[DIN / 2];
    for (int i = threadIdx.x; i < 256 * DIN; i += 256)
        sw[(i >> 5) * 33 + (i & 31)] = W[i];
    __syncthreads();
    #pragma unroll
    for (int k = 0; k < DIN / 2; k++) w[k] = pack2(sw[o * 33 + 2 * k], sw[o * 33 + 2 * k + 1]);

    for (int base = blockIdx.x * NL_TILE; base < N_NODES; base += gridDim.x * NL_TILE) {
        int nn = min(NL_TILE, N_NODES - base);
        __syncthreads();
        for (int i = threadIdx.x; i < nn * DIN; i += 256)
            sx[i] = x[base * DIN + i];
        __syncthreads();
        for (int j = 0; j < nn; j++) {
            const unsigned long long* sxp = (const unsigned long long*)(sx + j * DIN);
            unsigned long long aA = 0, aB = 0;
            #pragma unroll
            for (int k = 0; k < DIN / 2; k += 2) {
                aA = fma2(w[k],     sxp[k],     aA);
                aB = fma2(w[k + 1], sxp[k + 1], aB);
            }
            outh[(size_t)(base + j) * HC + o] = __float2half(hsum2(aA) + hsum2(aB));
        }
    }
}

// ---------------- K5: node-centric fused GAT (head-per-8-lane, 2-edge unroll) --------------
__global__ void __launch_bounds__(256) k_gat_node(const float* __restrict__ att) {
    __shared__ float satt[HC];
    if (threadIdx.x < HC) satt[threadIdx.x] = att[threadIdx.x];
    __syncthreads();
    int n = blockIdx.x * 8 + (threadIdx.x >> 5);
    if (n >= N_NODES) return;
    int l = threadIdx.x & 31;
    int h = l >> 3, g = l & 7;
    int off = h * C + 8 * g;
    int beg = g_rowptr[n], end = g_rowptr[n + 1];

    F8 b = ldh8(g_xr + (size_t)n * HC + off);
    float4 tlo = *(const float4*)(satt + off);
    float4 thi = *(const float4*)(satt + off + 4);

    float4 acc_lo = {0.f,0.f,0.f,0.f}, acc_hi = {0.f,0.f,0.f,0.f};
    float den = 0.f;

    #define GAT_LOGIT8(A, P) do {                                              \
        float v_;                                                              \
        v_ = A.lo.x + b.lo.x; v_ = v_ > 0.f ? v_ : 0.2f * v_; P += v_ * tlo.x; \
        v_ = A.lo.y + b.lo.y; v_ = v_ > 0.f ? v_ : 0.2f * v_; P += v_ * tlo.y; \
        v_ = A.lo.z + b.lo.z; v_ = v_ > 0.f ? v_ : 0.2f * v_; P += v_ * tlo.z; \
        v_ = A.lo.w + b.lo.w; v_ = v_ > 0.f ? v_ : 0.2f * v_; P += v_ * tlo.w; \
        v_ = A.hi.x + b.hi.x; v_ = v_ > 0.f ? v_ : 0.2f * v_; P += v_ * thi.x; \
        v_ = A.hi.y + b.hi.y; v_ = v_ > 0.f ? v_ : 0.2f * v_; P += v_ * thi.y; \
        v_ = A.hi.z + b.hi.z; v_ = v_ > 0.f ? v_ : 0.2f * v_; P += v_ * thi.z; \
        v_ = A.hi.w + b.hi.w; v_ = v_ > 0.f ? v_ : 0.2f * v_; P += v_ * thi.w; \
    } while (0)

    #define GAT_ACCUM8(A, EX) do {                                           \
        acc_lo.x += A.lo.x * EX; acc_lo.y += A.lo.y * EX;                    \
        acc_lo.z += A.lo.z * EX; acc_lo.w += A.lo.w * EX;                    \
        acc_hi.x += A.hi.x * EX; acc_hi.y += A.hi.y * EX;                    \
        acc_hi.z += A.hi.z * EX; acc_hi.w += A.hi.w * EX;                    \
    } while (0)

    int i = beg;
    for (; i + 1 < end; i += 2) {
        int srcA = __ldg(&g_csrc[i]);
        int srcB = __ldg(&g_csrc[i + 1]);
        F8 aA = ldh8(g_xl + (size_t)srcA * HC + off);
        F8 aB = ldh8(g_xl + (size_t)srcB * HC + off);
        float pA = 0.f, pB = 0.f;
        GAT_LOGIT8(aA, pA);
        GAT_LOGIT8(aB, pB);
        #pragma unroll
        for (int s = 4; s >= 1; s >>= 1) {
            pA += __shfl_xor_sync(0xffffffffu, pA, s);
            pB += __shfl_xor_sync(0xffffffffu, pB, s);
        }
        float exA = __expf(pA), exB = __expf(pB);
        GAT_ACCUM8(aA, exA);
        GAT_ACCUM8(aB, exB);
        den += exA + exB;
    }
    if (i < end) {
        int src = __ldg(&g_csrc[i]);
        F8 a = ldh8(g_xl + (size_t)src * HC + off);
        float p = 0.f;
        GAT_LOGIT8(a, p);
        #pragma unroll
        for (int s = 4; s >= 1; s >>= 1)
            p += __shfl_xor_sync(0xffffffffu, p, s);
        float ex = __expf(p);
        GAT_ACCUM8(a, ex);
        den += ex;
    }
    #undef GAT_LOGIT8
    #undef GAT_ACCUM8

    // normalize by this head's denom, then sum heads across lanes g, 8+g, 16+g, 24+g
    float inv = 1.0f / (den + 1e-16f);
    #define HEADSUM(F) do {                                                  \
        F *= inv;                                                            \
        F += __shfl_xor_sync(0xffffffffu, F, 8);                             \
        F += __shfl_xor_sync(0xffffffffu, F, 16);                            \
    } while (0)
    HEADSUM(acc_lo.x); HEADSUM(acc_lo.y); HEADSUM(acc_lo.z); HEADSUM(acc_lo.w);
    HEADSUM(acc_hi.x); HEADSUM(acc_hi.y); HEADSUM(acc_hi.z); HEADSUM(acc_hi.w);
    #undef HEADSUM

    if (l < 8) {                                 // lanes 0..7 write channels 8l..8l+8
        float deg = (float)(end - beg);
        float dinv = deg > 0.f ? rsqrtf(deg) : 0.f;
        float4 o0, o1;
        float m;
        m = 0.25f * acc_lo.x; m = m > 0.f ? m : expm1f(m); o0.x = m * dinv;
        m = 0.25f * acc_lo.y; m = m > 0.f ? m : expm1f(m); o0.y = m * dinv;
        m = 0.25f * acc_lo.z; m = m > 0.f ? m : expm1f(m); o0.z = m * dinv;
        m = 0.25f * acc_lo.w; m = m > 0.f ? m : expm1f(m); o0.w = m * dinv;
        m = 0.25f * acc_hi.x; m = m > 0.f ? m : expm1f(m); o1.x = m * dinv;
        m = 0.25f * acc_hi.y; m = m > 0.f ? m : expm1f(m); o1.y = m * dinv;
        m = 0.25f * acc_hi.z; m = m > 0.f ? m : expm1f(m); o1.z = m * dinv;
        m = 0.25f * acc_hi.w; m = m > 0.f ? m : expm1f(m); o1.w = m * dinv;
        float4* dst = (float4*)(g_h + (size_t)n * C + 8 * l);
        dst[0] = o0;
        dst[1] = o1;
    }
}

// ---------------- K6: node-centric GCN aggregate (2-edge unroll) ---------------------------
__global__ void __launch_bounds__(256) k_gcn_node() {
    int n = blockIdx.x * 8 + (threadIdx.x >> 5);
    if (n >= N_NODES) return;
    int l = threadIdx.x & 31;
    int beg = g_rowptr[n], end = g_rowptr[n + 1];
    float ax = 0.f, ay = 0.f;
    int i = beg;
    for (; i + 1 < end; i += 2) {
        int srcA = __ldg(&g_csrc[i]);
        int srcB = __ldg(&g_csrc[i + 1]);
        float2 vA = ((const float2*)(g_h + (size_t)srcA * C))[l];
        float2 vB = ((const float2*)(g_h + (size_t)srcB * C))[l];
        ax += vA.x + vB.x; ay += vA.y + vB.y;
    }
    if (i < end) {
        int src = __ldg(&g_csrc[i]);
        float2 v = ((const float2*)(g_h + (size_t)src * C))[l];
        ax += v.x; ay += v.y;
    }
    float deg = (float)(end - beg);
    float dinv = deg > 0.f ? rsqrtf(deg) : 0.f;
    float2 o; o.x = ax * dinv; o.y = ay * dinv;
    ((float2*)(g_agg + (size_t)n * C))[l] = o;
}

// ---------------- K7: final linear (f32x2) -------------------------------------------------
#define OL_TILE 8
__global__ void __launch_bounds__(128) k_out_linear(const float* __restrict__ Wg,
                                                    float* __restrict__ out) {
    __shared__ float sw[DOUT * 65];
    __shared__ float sh[OL_TILE * C];
    int o = threadIdx.x;
    unsigned long long wg[C / 2];
    for (int i = threadIdx.x; i < DOUT * C; i += 128)
        sw[(i >> 6) * 65 + (i & 63)] = Wg[i];
    __syncthreads();
    #pragma unroll
    for (int k = 0; k < C / 2; k++) wg[k] = pack2(sw[o * 65 + 2 * k], sw[o * 65 + 2 * k + 1]);

    for (int base = blockIdx.x * OL_TILE; base < N_NODES; base += gridDim.x * OL_TILE) {
        int nn = min(OL_TILE, N_NODES - base);
        __syncthreads();
        for (int i = threadIdx.x; i < nn * C; i += 128)
            sh[i] = g_agg[(size_t)base * C + i];
        __syncthreads();
        for (int j = 0; j < nn; j++) {
            const unsigned long long* shp = (const unsigned long long*)(sh + j * C);
            unsigned long long sA = 0, sB = 0;
            #pragma unroll
            for (int k = 0; k < C / 2; k += 2) {
                sA = fma2(wg[k],     shp[k],     sA);
                sB = fma2(wg[k + 1], shp[k + 1], sB);
            }
            out[(size_t)(base + j) * DOUT + o] = hsum2(sA) + hsum2(sB);
        }
    }
}

// ---------------- launch -------------------------------------------------------------------
extern "C" void kernel_launch(void* const* d_in, const int* in_sizes, int n_in,
                              void* d_out, int out_size) {
    const float* x   = (const float*)d_in[0];
    const void*  ei  = d_in[1];
    const float* Wl  = (const float*)d_in[2];
    const float* Wr  = (const float*)d_in[3];
    const float* att = (const float*)d_in[4];
    const float* Wg  = (const float*)d_in[5];
    float* out = (float*)d_out;
    (void)in_sizes; (void)n_in; (void)out_size;

    k_zero_cnt<<<(N_NODES + 255) / 256, 256>>>((const int*)ei);
    k_hist<<<(E_EDGES + 255) / 256, 256>>>(ei);
    k_chunk_sum<<<(NCHUNK + 255) / 256, 256>>>();
    k_scan_chunks<<<1, SCAN_T>>>();
    k_fill_rowptr<<<(NCHUNK + 255) / 256, 256>>>();
    k_fill<<<(E_EDGES + 255) / 256, 256>>>(ei);
    k_node_linear<<<dim3(1184, 2), 256>>>(x, Wl, Wr);
    k_gat_node<<<(N_NODES + 7) / 8, 256>>>(att);
    k_gcn_node<<<(N_NODES + 7) / 8, 256>>>();
    k_out_linear<<<1184, 128>>>(Wg, out);
}

// round 16
// speedup vs baseline: 1.0591x; 1.0190x over previous
#include <cuda_runtime.h>
#include <cuda_fp16.h>
#include <cstdint>

#define N_NODES 50000
#define E_EDGES 800000
#define NHEAD 4
#define C 64
#define DIN 32
#define DOUT 128
#define HC 256   // NHEAD * C

#define CHUNK 16
#define NCHUNK ((N_NODES + CHUNK - 1) / CHUNK)   // 3125

// ---------------- device scratch ----------------------------------------------------------
__device__ int    g_is64;
__device__ int    g_cnt[N_NODES];
__device__ int    g_chunksum[NCHUNK];
__device__ int    g_chunkpre[NCHUNK];
__device__ int    g_rowptr[N_NODES + 1];
__device__ int    g_cursor[N_NODES];
__device__ int    g_csrc[E_EDGES];
__device__ __half g_xl[N_NODES * HC];     // fp16 storage, fp32 math
__device__ __half g_xr[N_NODES * HC];
__device__ float  g_h[N_NODES * C];
__device__ float  g_agg[N_NODES * C];

// ---------------- helpers ------------------------------------------------------------------
__device__ __forceinline__ unsigned long long pack2(float lo, float hi) {
    unsigned long long r;
    asm("mov.b64 %0, {%1,%2};" : "=l"(r) : "f"(lo), "f"(hi));
    return r;
}
__device__ __forceinline__ unsigned long long fma2(unsigned long long a,
                                                   unsigned long long b,
                                                   unsigned long long c) {
    unsigned long long d;
    asm("fma.rn.f32x2 %0, %1, %2, %3;" : "=l"(d) : "l"(a), "l"(b), "l"(c));
    return d;
}
__device__ __forceinline__ float hsum2(unsigned long long v) {
    float lo, hi;
    asm("mov.b64 {%0,%1}, %2;" : "=f"(lo), "=f"(hi) : "l"(v));
    return lo + hi;
}
// 8 consecutive halves (16B aligned) -> two float4, by value (registerizable)
struct F8 { float4 lo, hi; };
__device__ __forceinline__ F8 ldh8(const __half* p) {
    uint4 raw = *(const uint4*)p;
    const __half2* h = (const __half2*)&raw;
    float2 f0 = __half22float2(h[0]);
    float2 f1 = __half22float2(h[1]);
    float2 f2 = __half22float2(h[2]);
    float2 f3 = __half22float2(h[3]);
    F8 r;
    r.lo = make_float4(f0.x, f0.y, f1.x, f1.y);
    r.hi = make_float4(f2.x, f2.y, f3.x, f3.y);
    return r;
}

// ---------------- K0: zero histogram + detect dtype (fused) --------------------------------
__global__ void k_zero_cnt(const int* __restrict__ ei32) {
    int i = blockIdx.x * blockDim.x + threadIdx.x;
    if (i < N_NODES) g_cnt[i] = 0;
    if (i == 0) {
        int odd_zero = 1;
        for (int j = 1; j < 64; j += 2)
            if (ei32[j] != 0) { odd_zero = 0; break; }
        g_is64 = odd_zero;   // int64 viewed as int32: odd positions all zero
    }
}

// ---------------- K1: degree histogram straight from ei (1 edge/thread) --------------------
__global__ void k_hist(const void* __restrict__ ei) {
    int e = blockIdx.x * blockDim.x + threadIdx.x;
    if (e >= E_EDGES) return;
    int d = g_is64 ? (int)((const long long*)ei)[E_EDGES + e]
                   : ((const int*)ei)[E_EDGES + e];
    atomicAdd(&g_cnt[d], 1);
}

// ---------------- K2a: per-chunk sums ------------------------------------------------------
__global__ void k_chunk_sum() {
    int c = blockIdx.x * blockDim.x + threadIdx.x;
    if (c >= NCHUNK) return;
    int b = c * CHUNK;
    int e = min(b + CHUNK, N_NODES);
    int s = 0;
    #pragma unroll 4
    for (int i = b; i < e; i++) s += g_cnt[i];
    g_chunksum[c] = s;
}

// ---------------- K2b: scan chunk sums in one block ----------------------------------------
#define SCAN_T 1024
#define PER_T  ((NCHUNK + SCAN_T - 1) / SCAN_T)   // 4
__global__ void __launch_bounds__(SCAN_T) k_scan_chunks() {
    __shared__ int part[SCAN_T];
    int t = threadIdx.x;
    int v[PER_T];
    int s = 0;
    #pragma unroll
    for (int j = 0; j < PER_T; j++) {
        int c = t * PER_T + j;
        v[j] = (c < NCHUNK) ? g_chunksum[c] : 0;
        s += v[j];
    }
    part[t] = s;
    __syncthreads();
    for (int off = 1; off < SCAN_T; off <<= 1) {
        int u = (t >= off) ? part[t - off] : 0;
        __syncthreads();
        part[t] += u;
        __syncthreads();
    }
    int pre = (t == 0) ? 0 : part[t - 1];
    #pragma unroll
    for (int j = 0; j < PER_T; j++) {
        int c = t * PER_T + j;
        if (c < NCHUNK) g_chunkpre[c] = pre;
        pre += v[j];
    }
    if (t == SCAN_T - 1) g_rowptr[N_NODES] = part[SCAN_T - 1];
}

// ---------------- K2c: expand rowptr/cursor ------------------------------------------------
__global__ void k_fill_rowptr() {
    int c = blockIdx.x * blockDim.x + threadIdx.x;
    if (c >= NCHUNK) return;
    int b = c * CHUNK;
    int e = min(b + CHUNK, N_NODES);
    int pre = g_chunkpre[c];
    for (int i = b; i < e; i++) {
        g_rowptr[i] = pre;
        g_cursor[i] = pre;
        pre += g_cnt[i];
    }
}

// ---------------- K3: CSR fill straight from ei (1 edge/thread) ----------------------------
__global__ void k_fill(const void* __restrict__ ei) {
    int e = blockIdx.x * blockDim.x + threadIdx.x;
    if (e >= E_EDGES) return;
    int s, d;
    if (g_is64) {
        const long long* p = (const long long*)ei;
        s = (int)p[e];
        d = (int)p[E_EDGES + e];
    } else {
        const int* p = (const int*)ei;
        s = p[e];
        d = p[E_EDGES + e];
    }
    int pos = atomicAdd(&g_cursor[d], 1);
    g_csrc[pos] = s;
}

// ---------------- K4: node linear, both matrices in ONE launch (blockIdx.y = which) --------
#define NL_TILE 16
__global__ void __launch_bounds__(256) k_node_linear(const float* __restrict__ x,
                                                     const float* __restrict__ Wl,
                                                     const float* __restrict__ Wr) {
    int which = blockIdx.y;
    const float* W = which ? Wr : Wl;
    __half* outh = which ? g_xr : g_xl;   // device-side selection (no host symbol)
    __shared__ float sw[256 * 33];
    __shared__ float sx[NL_TILE * DIN];
    int o = threadIdx.x;
    unsigned long long w[DIN / 2];
    for (int i = threadIdx.x; i < 256 * DIN; i += 256)
        sw[(i >> 5) * 33 + (i & 31)] = W[i];
    __syncthreads();
    #pragma unroll
    for (int k = 0; k < DIN / 2; k++) w[k] = pack2(sw[o * 33 + 2 * k], sw[o * 33 + 2 * k + 1]);

    for (int base = blockIdx.x * NL_TILE; base < N_NODES; base += gridDim.x * NL_TILE) {
        int nn = min(NL_TILE, N_NODES - base);
        __syncthreads();
        for (int i = threadIdx.x; i < nn * DIN; i += 256)
            sx[i] = x[base * DIN + i];
        __syncthreads();
        for (int j = 0; j < nn; j++) {
            const unsigned long long* sxp = (const unsigned long long*)(sx + j * DIN);
            unsigned long long aA = 0, aB = 0;
            #pragma unroll
            for (int k = 0; k < DIN / 2; k += 2) {
                aA = fma2(w[k],     sxp[k],     aA);
                aB = fma2(w[k + 1], sxp[k + 1], aB);
            }
            outh[(size_t)(base + j) * HC + o] = __float2half(hsum2(aA) + hsum2(aB));
        }
    }
}

// ---------------- K5: node-centric fused GAT (head-per-8-lane, 2-edge unroll) --------------
__global__ void __launch_bounds__(256) k_gat_node(const float* __restrict__ att) {
    __shared__ float satt[HC];
    if (threadIdx.x < HC) satt[threadIdx.x] = att[threadIdx.x];
    __syncthreads();
    int n = blockIdx.x * 8 + (threadIdx.x >> 5);
    if (n >= N_NODES) return;
    int l = threadIdx.x & 31;
    int h = l >> 3, g = l & 7;
    int off = h * C + 8 * g;
    int beg = g_rowptr[n], end = g_rowptr[n + 1];

    F8 b = ldh8(g_xr + (size_t)n * HC + off);
    float4 tlo = *(const float4*)(satt + off);
    float4 thi = *(const float4*)(satt + off + 4);

    float4 acc_lo = {0.f,0.f,0.f,0.f}, acc_hi = {0.f,0.f,0.f,0.f};
    float den = 0.f;

    #define GAT_LOGIT8(A, P) do {                                              \
        float v_;                                                              \
        v_ = A.lo.x + b.lo.x; v_ = v_ > 0.f ? v_ : 0.2f * v_; P += v_ * tlo.x; \
        v_ = A.lo.y + b.lo.y; v_ = v_ > 0.f ? v_ : 0.2f * v_; P += v_ * tlo.y; \
        v_ = A.lo.z + b.lo.z; v_ = v_ > 0.f ? v_ : 0.2f * v_; P += v_ * tlo.z; \
        v_ = A.lo.w + b.lo.w; v_ = v_ > 0.f ? v_ : 0.2f * v_; P += v_ * tlo.w; \
        v_ = A.hi.x + b.hi.x; v_ = v_ > 0.f ? v_ : 0.2f * v_; P += v_ * thi.x; \
        v_ = A.hi.y + b.hi.y; v_ = v_ > 0.f ? v_ : 0.2f * v_; P += v_ * thi.y; \
        v_ = A.hi.z + b.hi.z; v_ = v_ > 0.f ? v_ : 0.2f * v_; P += v_ * thi.z; \
        v_ = A.hi.w + b.hi.w; v_ = v_ > 0.f ? v_ : 0.2f * v_; P += v_ * thi.w; \
    } while (0)

    #define GAT_ACCUM8(A, EX) do {                                           \
        acc_lo.x += A.lo.x * EX; acc_lo.y += A.lo.y * EX;                    \
        acc_lo.z += A.lo.z * EX; acc_lo.w += A.lo.w * EX;                    \
        acc_hi.x += A.hi.x * EX; acc_hi.y += A.hi.y * EX;                    \
        acc_hi.z += A.hi.z * EX; acc_hi.w += A.hi.w * EX;                    \
    } while (0)

    int i = beg;
    for (; i + 1 < end; i += 2) {
        int srcA = __ldg(&g_csrc[i]);
        int srcB = __ldg(&g_csrc[i + 1]);
        F8 aA = ldh8(g_xl + (size_t)srcA * HC + off);
        F8 aB = ldh8(g_xl + (size_t)srcB * HC + off);
        float pA = 0.f, pB = 0.f;
        GAT_LOGIT8(aA, pA);
        GAT_LOGIT8(aB, pB);
        #pragma unroll
        for (int s = 4; s >= 1; s >>= 1) {
            pA += __shfl_xor_sync(0xffffffffu, pA, s);
            pB += __shfl_xor_sync(0xffffffffu, pB, s);
        }
        float exA = __expf(pA), exB = __expf(pB);
        GAT_ACCUM8(aA, exA);
        GAT_ACCUM8(aB, exB);
        den += exA + exB;
    }
    if (i < end) {
        int src = __ldg(&g_csrc[i]);
        F8 a = ldh8(g_xl + (size_t)src * HC + off);
        float p = 0.f;
        GAT_LOGIT8(a, p);
        #pragma unroll
        for (int s = 4; s >= 1; s >>= 1)
            p += __shfl_xor_sync(0xffffffffu, p, s);
        float ex = __expf(p);
        GAT_ACCUM8(a, ex);
        den += ex;
    }
    #undef GAT_LOGIT8
    #undef GAT_ACCUM8

    // normalize by this head's denom, then sum heads across lanes g, 8+g, 16+g, 24+g
    float inv = 1.0f / (den + 1e-16f);
    #define HEADSUM(F) do {                                                  \
        F *= inv;                                                            \
        F += __shfl_xor_sync(0xffffffffu, F, 8);                             \
        F += __shfl_xor_sync(0xffffffffu, F, 16);                            \
    } while (0)
    HEADSUM(acc_lo.x); HEADSUM(acc_lo.y); HEADSUM(acc_lo.z); HEADSUM(acc_lo.w);
    HEADSUM(acc_hi.x); HEADSUM(acc_hi.y); HEADSUM(acc_hi.z); HEADSUM(acc_hi.w);
    #undef HEADSUM

    if (l < 8) {                                 // lanes 0..7 write channels 8l..8l+8
        float deg = (float)(end - beg);
        float dinv = deg > 0.f ? rsqrtf(deg) : 0.f;
        float4 o0, o1;
        float m;
        m = 0.25f * acc_lo.x; m = m > 0.f ? m : expm1f(m); o0.x = m * dinv;
        m = 0.25f * acc_lo.y; m = m > 0.f ? m : expm1f(m); o0.y = m * dinv;
        m = 0.25f * acc_lo.z; m = m > 0.f ? m : expm1f(m); o0.z = m * dinv;
        m = 0.25f * acc_lo.w; m = m > 0.f ? m : expm1f(m); o0.w = m * dinv;
        m = 0.25f * acc_hi.x; m = m > 0.f ? m : expm1f(m); o1.x = m * dinv;
        m = 0.25f * acc_hi.y; m = m > 0.f ? m : expm1f(m); o1.y = m * dinv;
        m = 0.25f * acc_hi.z; m = m > 0.f ? m : expm1f(m); o1.z = m * dinv;
        m = 0.25f * acc_hi.w; m = m > 0.f ? m : expm1f(m); o1.w = m * dinv;
        float4* dst = (float4*)(g_h + (size_t)n * C + 8 * l);
        dst[0] = o0;
        dst[1] = o1;
    }
}

// ---------------- K6: node-centric GCN aggregate (2-edge unroll) ---------------------------
__global__ void __launch_bounds__(256) k_gcn_node() {
    int n = blockIdx.x * 8 + (threadIdx.x >> 5);
    if (n >= N_NODES) return;
    int l = threadIdx.x & 31;
    int beg = g_rowptr[n], end = g_rowptr[n + 1];
    float ax = 0.f, ay = 0.f;
    int i = beg;
    for (; i + 1 < end; i += 2) {
        int srcA = __ldg(&g_csrc[i]);
        int srcB = __ldg(&g_csrc[i + 1]);
        float2 vA = ((const float2*)(g_h + (size_t)srcA * C))[l];
        float2 vB = ((const float2*)(g_h + (size_t)srcB * C))[l];
        ax += vA.x + vB.x; ay += vA.y + vB.y;
    }
    if (i < end) {
        int src = __ldg(&g_csrc[i]);
        float2 v = ((const float2*)(g_h + (size_t)src * C))[l];
        ax += v.x; ay += v.y;
    }
    float deg = (float)(end - beg);
    float dinv = deg > 0.f ? rsqrtf(deg) : 0.f;
    float2 o; o.x = ax * dinv; o.y = ay * dinv;
    ((float2*)(g_agg + (size_t)n * C))[l] = o;
}

// ---------------- K7: final linear (f32x2) -------------------------------------------------
#define OL_TILE 8
__global__ void __launch_bounds__(128) k_out_linear(const float* __restrict__ Wg,
                                                    float* __restrict__ out) {
    __shared__ float sw[DOUT * 65];
    __shared__ float sh[OL_TILE * C];
    int o = threadIdx.x;
    unsigned long long wg[C / 2];
    for (int i = threadIdx.x; i < DOUT * C; i += 128)
        sw[(i >> 6) * 65 + (i & 63)] = Wg[i];
    __syncthreads();
    #pragma unroll
    for (int k = 0; k < C / 2; k++) wg[k] = pack2(sw[o * 65 + 2 * k], sw[o * 65 + 2 * k + 1]);

    for (int base = blockIdx.x * OL_TILE; base < N_NODES; base += gridDim.x * OL_TILE) {
        int nn = min(OL_TILE, N_NODES - base);
        __syncthreads();
        for (int i = threadIdx.x; i < nn * C; i += 128)
            sh[i] = g_agg[(size_t)base * C + i];
        __syncthreads();
        for (int j = 0; j < nn; j++) {
            const unsigned long long* shp = (const unsigned long long*)(sh + j * C);
            unsigned long long sA = 0, sB = 0;
            #pragma unroll
            for (int k = 0; k < C / 2; k += 2) {
                sA = fma2(wg[k],     shp[k],     sA);
                sB = fma2(wg[k + 1], shp[k + 1], sB);
            }
            out[(size_t)(base + j) * DOUT + o] = hsum2(sA) + hsum2(sB);
        }
    }
}

// ---------------- launch: fork CSR build onto a side stream, overlap with node linear ------
extern "C" void kernel_launch(void* const* d_in, const int* in_sizes, int n_in,
                              void* d_out, int out_size) {
    const float* x   = (const float*)d_in[0];
    const void*  ei  = d_in[1];
    const float* Wl  = (const float*)d_in[2];
    const float* Wr  = (const float*)d_in[3];
    const float* att = (const float*)d_in[4];
    const float* Wg  = (const float*)d_in[5];
    float* out = (float*)d_out;
    (void)in_sizes; (void)n_in; (void)out_size;

    // One-time host-side resource setup (streams/events only — no device memory).
    // GPU work per call is identical; this only enables a parallel branch in the graph.
    static cudaStream_t s2 = nullptr;
    static cudaEvent_t evFork = nullptr, evJoin = nullptr;
    if (s2 == nullptr) {
        cudaStreamCreateWithFlags(&s2, cudaStreamNonBlocking);
        cudaEventCreateWithFlags(&evFork, cudaEventDisableTiming);
        cudaEventCreateWithFlags(&evJoin, cudaEventDisableTiming);
    }

    // Fork: side stream joins the (captured) main stream's timeline.
    cudaEventRecord(evFork, 0);
    cudaStreamWaitEvent(s2, evFork, 0);

    // Branch A (s2): CSR build chain — independent of node features.
    k_zero_cnt<<<(N_NODES + 255) / 256, 256, 0, s2>>>((const int*)ei);
    k_hist<<<(E_EDGES + 255) / 256, 256, 0, s2>>>(ei);
    k_chunk_sum<<<(NCHUNK + 255) / 256, 256, 0, s2>>>();
    k_scan_chunks<<<1, SCAN_T, 0, s2>>>();
    k_fill_rowptr<<<(NCHUNK + 255) / 256, 256, 0, s2>>>();
    k_fill<<<(E_EDGES + 255) / 256, 256, 0, s2>>>(ei);

    // Branch B (main stream): node linear — runs concurrently with branch A.
    k_node_linear<<<dim3(1184, 2), 256>>>(x, Wl, Wr);

    // Join: gat needs both CSR and xl/xr.
    cudaEventRecord(evJoin, s2);
    cudaStreamWaitEvent(0, evJoin, 0);

    k_gat_node<<<(N_NODES + 7) / 8, 256>>>(att);
    k_gcn_node<<<(N_NODES + 7) / 8, 256>>>();
    k_out_linear<<<1184, 128>>>(Wg, out);
}